// round 6
// baseline (speedup 1.0000x reference)
#include <cuda_runtime.h>
#include <cuda_fp16.h>
#include <cstdint>
#include <cstddef>

#define T_SEQ 1024
#define HID   256
#define ROWS  64

// ---------------------------------------------------------------------------
// Fragment-layout exchange buffers. Element u32 = (half k_even, half k_odd).
// h:   [parity2][bg4][w8][s2][pg2][q4][r16]
// seq: [t1024] [bg4][w8][s2][pg2][q4][r16]
// ---------------------------------------------------------------------------
__device__ uint32_t g_hf_hi[2 * 4 * 8 * 2 * 2 * 4 * 16];
__device__ uint32_t g_hf_lo[2 * 4 * 8 * 2 * 2 * 4 * 16];
__device__ uint32_t g_sA_hi[T_SEQ * 4 * 8 * 2 * 2 * 4 * 16];   // 16 MB each
__device__ uint32_t g_sA_lo[T_SEQ * 4 * 8 * 2 * 2 * 4 * 16];
__device__ uint32_t g_sB_hi[T_SEQ * 4 * 8 * 2 * 2 * 4 * 16];
__device__ uint32_t g_sB_lo[T_SEQ * 4 * 8 * 2 * 2 * 4 * 16];
__device__ uint32_t g_mbits[ROWS * 32];                        // mask bitfield
__device__ unsigned g_flag[3 * 4 * 32];                        // [layer][bg][cg]

static __device__ __forceinline__ int hidx(int p, int bg, int w, int s, int pg, int q, int r)
{
    return (((((p * 4 + bg) * 8 + w) * 2 + s) * 2 + pg) * 4 + q) * 16 + r;
}
static __device__ __forceinline__ int sidx(int t, int bg, int w, int s, int pg, int q, int r)
{
    return (((((t * 4 + bg) * 8 + w) * 2 + s) * 2 + pg) * 4 + q) * 16 + r;
}

// ---------------------------------------------------------------------------
__global__ void init_kernel(const float* __restrict__ x)
{
    if (blockIdx.x == 0) {
        for (int i = threadIdx.x; i < 3 * 4 * 32; i += blockDim.x) g_flag[i] = 0u;
    }
    int warp = (int)((blockIdx.x * blockDim.x + threadIdx.x) >> 5);
    int lane = threadIdx.x & 31;
    if (warp < ROWS * T_SEQ) {
        const float4* p = reinterpret_cast<const float4*>(x) + (size_t)warp * 32;
        float4 v = p[lane];
        bool nz = (v.x != 0.0f) || (v.y != 0.0f) || (v.z != 0.0f) || (v.w != 0.0f);
        unsigned bl = __ballot_sync(0xffffffffu, nz);
        if (lane == 0 && bl) {
            int row = warp >> 10, t = warp & 1023;
            atomicOr(&g_mbits[row * 32 + (t >> 5)], 1u << (t & 31));  // idempotent
        }
    }
}

// ---------------------------------------------------------------------------
static __device__ __forceinline__ void split2(float a, float b, uint32_t& hi, uint32_t& lo)
{
    __half h0 = __float2half_rn(a), h1 = __float2half_rn(b);
    __half l0 = __float2half_rn(a - __half2float(h0));
    __half l1 = __float2half_rn(b - __half2float(h1));
    __half2 H = __halves2half2(h0, h1), L = __halves2half2(l0, l1);
    hi = *reinterpret_cast<uint32_t*>(&H);
    lo = *reinterpret_cast<uint32_t*>(&L);
}

static __device__ __forceinline__ void mma16816(float* d, uint32_t a0, uint32_t a1,
                                                uint32_t a2, uint32_t a3,
                                                uint32_t b0, uint32_t b1)
{
    asm volatile("mma.sync.aligned.m16n8k16.row.col.f32.f16.f16.f32 "
                 "{%0,%1,%2,%3}, {%4,%5,%6,%7}, {%8,%9}, {%0,%1,%2,%3};"
                 : "+f"(d[0]), "+f"(d[1]), "+f"(d[2]), "+f"(d[3])
                 : "r"(a0), "r"(a1), "r"(a2), "r"(a3), "r"(b0), "r"(b1));
}

static __device__ __forceinline__ float wu_elem(const float* __restrict__ W,
                                                const float* __restrict__ U,
                                                int Kin, int k, int gcol)
{
    return (k < Kin) ? W[(size_t)k * 1024 + gcol] : U[(size_t)(k - Kin) * 1024 + gcol];
}

static __device__ __forceinline__ unsigned ld_acq(const unsigned* p)
{
    unsigned v;
    asm volatile("ld.acquire.gpu.global.u32 %0, [%1];" : "=r"(v) : "l"(p) : "memory");
    return v;
}
static __device__ __forceinline__ void st_rel(unsigned* p, unsigned v)
{
    asm volatile("st.release.gpu.global.u32 [%0], %1;" :: "l"(p), "r"(v) : "memory");
}
static __device__ __forceinline__ void st_cg_u16(unsigned short* p, unsigned short v)
{
    asm volatile("st.global.cg.u16 [%0], %1;" :: "l"(p), "h"(v) : "memory");
}
static __device__ __forceinline__ uint32_t ld_cg_u32(const uint32_t* p)
{
    uint32_t v;
    asm volatile("ld.global.cg.u32 %0, [%1];" : "=r"(v) : "l"(p));
    return v;
}

static __device__ __forceinline__ float sigx(float x)
{
    return __fdividef(1.0f, 1.0f + __expf(-x));
}
static __device__ __forceinline__ float tanhx(float x)
{
    return __fdividef(2.0f, 1.0f + __expf(-2.0f * x)) - 1.0f;
}

// ---------------------------------------------------------------------------
// Persistent tensor-core masked-LSTM layer. 128 blocks: bg=blockIdx&3 (16 rows),
// cg=blockIdx>>2 (8 units -> 32 gate cols). 8 warps split K; warp w's h-slice =
// units [32w,32w+32) = outputs of producer blocks (bg, 4w..4w+3) -> per-warp
// flag poll, fragment-direct ld.cg into mma registers. x software-pipelined.
// ---------------------------------------------------------------------------
template <int LAYER>
__global__ void __launch_bounds__(256, 1)
lstm_tc(const float* __restrict__ x0,
        const float* __restrict__ W, const float* __restrict__ U,
        const float* __restrict__ bias)
{
    constexpr int XSTEPS = (LAYER == 0) ? 1 : 2;
    constexpr int KIN    = 128 * XSTEPS;
    constexpr int KSTEPS = XSTEPS + 2;

    __shared__ float    p_sh[8 * 16 * 36];
    __shared__ uint32_t msk_sh[16 * 32];

    const int tid  = threadIdx.x;
    const int w    = tid >> 5;
    const int lane = tid & 31;
    const int bg   = blockIdx.x & 3;
    const int cg   = blockIdx.x >> 2;
    const int row0 = bg * 16;
    const int q    = lane & 3;
    const int nl   = lane >> 2;

    // ---- stage mask bits (2KB, once) ----
    for (int i = tid; i < 512; i += 256)
        msk_sh[i] = g_mbits[(row0 + (i >> 5)) * 32 + (i & 31)];

    // ---- B (weight) fragments in registers, hi/lo split ----
    auto kbase = [&](int s) -> int {
        return (s < XSTEPS) ? (w * (KIN / 8) + 16 * s)
                            : (KIN + w * 32 + 16 * (s - XSTEPS));
    };
    uint32_t Bhi[4][KSTEPS][2], Blo[4][KSTEPS][2];
    #pragma unroll
    for (int i = 0; i < 4; i++) {
        int gcol = i * 256 + cg * 8 + nl;
        #pragma unroll
        for (int s = 0; s < KSTEPS; s++) {
            int kb = kbase(s) + 2 * q;
            split2(wu_elem(W, U, KIN, kb,     gcol),
                   wu_elem(W, U, KIN, kb + 1, gcol), Bhi[i][s][0], Blo[i][s][0]);
            split2(wu_elem(W, U, KIN, kb + 8, gcol),
                   wu_elem(W, U, KIN, kb + 9, gcol), Bhi[i][s][1], Blo[i][s][1]);
        }
    }

    // ---- gate-thread constants/state (tid<128: row gr, unit gu) ----
    const int gr = tid >> 3, gu = tid & 7;
    float bias4[4] = {0, 0, 0, 0};
    if (tid < 128) {
        #pragma unroll
        for (int g = 0; g < 4; g++) bias4[g] = bias[g * 256 + cg * 8 + gu];
    }
    float c_reg = 0.0f, h_reg = 0.0f;

    unsigned* myflag = &g_flag[LAYER * 128 + bg * 32 + cg];
    const unsigned* pollflag = &g_flag[LAYER * 128 + bg * 32 + 4 * w];

    const uint32_t* seq_in_hi = (LAYER == 1) ? g_sA_hi : g_sB_hi;
    const uint32_t* seq_in_lo = (LAYER == 1) ? g_sA_lo : g_sB_lo;
    uint32_t* seq_out_hi = (LAYER == 0) ? g_sA_hi : g_sB_hi;
    uint32_t* seq_out_lo = (LAYER == 0) ? g_sA_lo : g_sB_lo;

    // ---- x raw pipeline registers (loaded one step ahead) ----
    float2   xrf[4];                 // LAYER 0
    uint32_t xrh[2][4], xrl[2][4];   // LAYER 1/2

    auto load_x = [&](int tt) {
        if (LAYER == 0) {
            const float* xp  = x0 + ((size_t)(row0 + nl) * T_SEQ + tt) * 128 + w * 16;
            const float* xp8 = x0 + ((size_t)(row0 + nl + 8) * T_SEQ + tt) * 128 + w * 16;
            xrf[0] = *reinterpret_cast<const float2*>(xp  + 2 * q);
            xrf[1] = *reinterpret_cast<const float2*>(xp8 + 2 * q);
            xrf[2] = *reinterpret_cast<const float2*>(xp  + 8 + 2 * q);
            xrf[3] = *reinterpret_cast<const float2*>(xp8 + 8 + 2 * q);
        } else {
            int base = sidx(tt, bg, w, 0, 0, 0, 0);
            #pragma unroll
            for (int s = 0; s < 2; s++) {
                xrh[s][0] = seq_in_hi[base + s * 128 + q * 16 + nl];
                xrh[s][1] = seq_in_hi[base + s * 128 + q * 16 + nl + 8];
                xrh[s][2] = seq_in_hi[base + s * 128 + 64 + q * 16 + nl];
                xrh[s][3] = seq_in_hi[base + s * 128 + 64 + q * 16 + nl + 8];
                xrl[s][0] = seq_in_lo[base + s * 128 + q * 16 + nl];
                xrl[s][1] = seq_in_lo[base + s * 128 + q * 16 + nl + 8];
                xrl[s][2] = seq_in_lo[base + s * 128 + 64 + q * 16 + nl];
                xrl[s][3] = seq_in_lo[base + s * 128 + 64 + q * 16 + nl + 8];
            }
        }
    };

    load_x(0);

    for (int t = 0; t < T_SEQ; t++) {
        // ---- materialize current x fragments, then prefetch next step's raw x ----
        uint32_t fxh[XSTEPS][4], fxl[XSTEPS][4];
        if (LAYER == 0) {
            #pragma unroll
            for (int j = 0; j < 4; j++) split2(xrf[j].x, xrf[j].y, fxh[0][j], fxl[0][j]);
        } else {
            #pragma unroll
            for (int s = 0; s < 2; s++)
                #pragma unroll
                for (int j = 0; j < 4; j++) { fxh[s][j] = xrh[s][j]; fxl[s][j] = xrl[s][j]; }
        }
        if (t + 1 < T_SEQ) load_x(t + 1);

        // ---- x-part MMAs (off the h critical chain) ----
        float D[4][4];
        #pragma unroll
        for (int i = 0; i < 4; i++)
            #pragma unroll
            for (int j = 0; j < 4; j++) D[i][j] = 0.0f;

        #pragma unroll
        for (int s = 0; s < XSTEPS; s++)
            #pragma unroll
            for (int i = 0; i < 4; i++) {
                mma16816(D[i], fxh[s][0], fxh[s][1], fxh[s][2], fxh[s][3],
                         Bhi[i][s][0], Bhi[i][s][1]);
                mma16816(D[i], fxl[s][0], fxl[s][1], fxl[s][2], fxl[s][3],
                         Bhi[i][s][0], Bhi[i][s][1]);
                mma16816(D[i], fxh[s][0], fxh[s][1], fxh[s][2], fxh[s][3],
                         Blo[i][s][0], Blo[i][s][1]);
            }

        // ---- per-warp: wait for this warp's 4 producers, then h-frag loads + MMAs ----
        if (t > 0) {
            unsigned tgt = (unsigned)t;
            for (;;) {
                unsigned v = (lane < 4) ? ld_acq(pollflag + lane) : tgt;
                if (__all_sync(0xffffffffu, v >= tgt)) break;
            }
            int p = t & 1;
            int hb = hidx(p, bg, w, 0, 0, 0, 0);
            uint32_t ahh[2][4], ahl[2][4];
            #pragma unroll
            for (int s = 0; s < 2; s++) {
                ahh[s][0] = ld_cg_u32(&g_hf_hi[hb + s * 128 + q * 16 + nl]);
                ahh[s][1] = ld_cg_u32(&g_hf_hi[hb + s * 128 + q * 16 + nl + 8]);
                ahh[s][2] = ld_cg_u32(&g_hf_hi[hb + s * 128 + 64 + q * 16 + nl]);
                ahh[s][3] = ld_cg_u32(&g_hf_hi[hb + s * 128 + 64 + q * 16 + nl + 8]);
                ahl[s][0] = ld_cg_u32(&g_hf_lo[hb + s * 128 + q * 16 + nl]);
                ahl[s][1] = ld_cg_u32(&g_hf_lo[hb + s * 128 + q * 16 + nl + 8]);
                ahl[s][2] = ld_cg_u32(&g_hf_lo[hb + s * 128 + 64 + q * 16 + nl]);
                ahl[s][3] = ld_cg_u32(&g_hf_lo[hb + s * 128 + 64 + q * 16 + nl + 8]);
            }
            #pragma unroll
            for (int s = 0; s < 2; s++) {
                int ks = XSTEPS + s;
                #pragma unroll
                for (int i = 0; i < 4; i++) {
                    mma16816(D[i], ahh[s][0], ahh[s][1], ahh[s][2], ahh[s][3],
                             Bhi[i][ks][0], Bhi[i][ks][1]);
                    mma16816(D[i], ahl[s][0], ahl[s][1], ahl[s][2], ahl[s][3],
                             Bhi[i][ks][0], Bhi[i][ks][1]);
                    mma16816(D[i], ahh[s][0], ahh[s][1], ahh[s][2], ahh[s][3],
                             Blo[i][ks][0], Blo[i][ks][1]);
                }
            }
        }

        // ---- split-K partials to smem ----
        #pragma unroll
        for (int i = 0; i < 4; i++) {
            *reinterpret_cast<float2*>(&p_sh[(w * 16 + nl) * 36 + i * 8 + 2 * q]) =
                make_float2(D[i][0], D[i][1]);
            *reinterpret_cast<float2*>(&p_sh[(w * 16 + nl + 8) * 36 + i * 8 + 2 * q]) =
                make_float2(D[i][2], D[i][3]);
        }
        __syncthreads();

        // ---- gates: reduce partials + state update + publish ----
        if (tid < 128) {
            float z[4];
            #pragma unroll
            for (int g = 0; g < 4; g++) {
                float acc = bias4[g];
                #pragma unroll
                for (int w8 = 0; w8 < 8; w8++)
                    acc += p_sh[(w8 * 16 + gr) * 36 + g * 8 + gu];
                z[g] = acc;
            }
            float si = sigx(z[0]), sf = sigx(z[1]), so = sigx(z[3]);
            float cn = sf * c_reg + si * tanhx(z[2]);
            float hn = so * tanhx(cn);
            bool m = (msk_sh[gr * 32 + (t >> 5)] >> (t & 31)) & 1u;
            if (!m) { cn = c_reg; hn = h_reg; }
            c_reg = cn; h_reg = hn;

            int j  = cg * 8 + gu;
            int jw = j >> 5, js = (j >> 4) & 1, jpg = (j >> 3) & 1, jq = (j >> 1) & 3, jh = j & 1;
            __half hh = __float2half_rn(hn);
            __half hl = __float2half_rn(hn - __half2float(hh));
            int hi_i = hidx((t + 1) & 1, bg, jw, js, jpg, jq, gr);
            st_cg_u16(reinterpret_cast<unsigned short*>(g_hf_hi) + hi_i * 2 + jh,
                      __half_as_ushort(hh));
            st_cg_u16(reinterpret_cast<unsigned short*>(g_hf_lo) + hi_i * 2 + jh,
                      __half_as_ushort(hl));
            if (LAYER < 2) {
                int si_i = sidx(t, bg, jw, js, jpg, jq, gr);
                st_cg_u16(reinterpret_cast<unsigned short*>(seq_out_hi) + si_i * 2 + jh,
                          __half_as_ushort(hh));
                st_cg_u16(reinterpret_cast<unsigned short*>(seq_out_lo) + si_i * 2 + jh,
                          __half_as_ushort(hl));
            }
        }
        __syncthreads();
        if (tid == 0) st_rel(myflag, (unsigned)(t + 1));
    }
}

// ---------------------------------------------------------------------------
__global__ void final_kernel(const float* __restrict__ dw,
                             const float* __restrict__ db,
                             float* __restrict__ out)
{
    int p = blockIdx.x, lane = threadIdx.x;
    int rA = 2 * p, rB = 2 * p + 1;
    float s = 0.0f;
    for (int jj = lane; jj < 128; jj += 32) {
        int j = 2 * jj;
        int jw = j >> 5, js = (j >> 4) & 1, jpg = (j >> 3) & 1, jq = (j >> 1) & 3;
        int iA = hidx(0, rA >> 4, jw, js, jpg, jq, rA & 15);
        int iB = hidx(0, rB >> 4, jw, js, jpg, jq, rB & 15);
        __half2 ah = *reinterpret_cast<__half2*>(&g_hf_hi[iA]);
        __half2 al = *reinterpret_cast<__half2*>(&g_hf_lo[iA]);
        __half2 bh = *reinterpret_cast<__half2*>(&g_hf_hi[iB]);
        __half2 bl = *reinterpret_cast<__half2*>(&g_hf_lo[iB]);
        float a0 = __low2float(ah)  + __low2float(al);
        float a1 = __high2float(ah) + __high2float(al);
        float b0 = __low2float(bh)  + __low2float(bl);
        float b1 = __high2float(bh) + __high2float(bl);
        float d0 = a0 - b0, d1 = a1 - b1;
        s += d0 * d0 + d1 * d1;
    }
    #pragma unroll
    for (int off = 16; off; off >>= 1) s += __shfl_xor_sync(0xffffffffu, s, off);
    if (lane == 0) {
        float dist = sqrtf(s);
        dist = fminf(fmaxf(dist, 1e-7f), 1e7f);
        out[p] = 1.0f / (1.0f + expf(-(dist * dw[0] + db[0])));
    }
}

// ---------------------------------------------------------------------------
extern "C" void kernel_launch(void* const* d_in, const int* in_sizes, int n_in,
                              void* d_out, int out_size)
{
    (void)in_sizes; (void)n_in; (void)out_size;
    const float* x  = (const float*)d_in[0];
    const float* W0 = (const float*)d_in[1];
    const float* U0 = (const float*)d_in[2];
    const float* b0 = (const float*)d_in[3];
    const float* W1 = (const float*)d_in[4];
    const float* U1 = (const float*)d_in[5];
    const float* b1 = (const float*)d_in[6];
    const float* W2 = (const float*)d_in[7];
    const float* U2 = (const float*)d_in[8];
    const float* b2 = (const float*)d_in[9];
    const float* dw = (const float*)d_in[10];
    const float* db = (const float*)d_in[11];
    float* out = (float*)d_out;

    init_kernel<<<8192, 256>>>(x);

    lstm_tc<0><<<128, 256>>>(x, W0, U0, b0);
    lstm_tc<1><<<128, 256>>>(x, W1, U1, b1);
    lstm_tc<2><<<128, 256>>>(x, W2, U2, b2);

    final_kernel<<<32, 32>>>(dw, db, out);
}

// round 7
// speedup vs baseline: 1.0805x; 1.0805x over previous
#include <cuda_runtime.h>
#include <cuda_fp16.h>
#include <cstdint>
#include <cstddef>

#define T_SEQ 1024
#define HID   256
#define ROWS  64

// ---------------------------------------------------------------------------
// Fragment-layout exchange buffers. Element u32 = (half k_even, half k_odd).
// h:   [parity2][bg4][w8][s2][pg2][q4][r16]
// seq: [t1024] [bg4][w8][s2][pg2][q4][r16]
// ---------------------------------------------------------------------------
__device__ uint32_t g_hf_hi[2 * 4 * 8 * 2 * 2 * 4 * 16];
__device__ uint32_t g_hf_lo[2 * 4 * 8 * 2 * 2 * 4 * 16];
__device__ uint32_t g_sA_hi[T_SEQ * 4 * 8 * 2 * 2 * 4 * 16];   // 16 MB each
__device__ uint32_t g_sA_lo[T_SEQ * 4 * 8 * 2 * 2 * 4 * 16];
__device__ uint32_t g_sB_hi[T_SEQ * 4 * 8 * 2 * 2 * 4 * 16];
__device__ uint32_t g_sB_lo[T_SEQ * 4 * 8 * 2 * 2 * 4 * 16];
__device__ uint32_t g_mbits[ROWS * 32];                        // mask bitfield
__device__ unsigned g_flag[3 * 4 * 32];                        // [layer][bg][cg]

static __device__ __forceinline__ int hidx(int p, int bg, int w, int s, int pg, int q, int r)
{
    return (((((p * 4 + bg) * 8 + w) * 2 + s) * 2 + pg) * 4 + q) * 16 + r;
}
static __device__ __forceinline__ int sidx(int t, int bg, int w, int s, int pg, int q, int r)
{
    return (((((t * 4 + bg) * 8 + w) * 2 + s) * 2 + pg) * 4 + q) * 16 + r;
}

// ---------------------------------------------------------------------------
__global__ void init_kernel(const float* __restrict__ x)
{
    if (blockIdx.x == 0) {
        for (int i = threadIdx.x; i < 3 * 4 * 32; i += blockDim.x) g_flag[i] = 0u;
    }
    int warp = (int)((blockIdx.x * blockDim.x + threadIdx.x) >> 5);
    int lane = threadIdx.x & 31;
    if (warp < ROWS * T_SEQ) {
        const float4* p = reinterpret_cast<const float4*>(x) + (size_t)warp * 32;
        float4 v = p[lane];
        bool nz = (v.x != 0.0f) || (v.y != 0.0f) || (v.z != 0.0f) || (v.w != 0.0f);
        unsigned bl = __ballot_sync(0xffffffffu, nz);
        if (lane == 0 && bl) {
            int row = warp >> 10, t = warp & 1023;
            atomicOr(&g_mbits[row * 32 + (t >> 5)], 1u << (t & 31));  // idempotent
        }
    }
}

// ---------------------------------------------------------------------------
static __device__ __forceinline__ void split2(float a, float b, uint32_t& hi, uint32_t& lo)
{
    __half h0 = __float2half_rn(a), h1 = __float2half_rn(b);
    __half l0 = __float2half_rn(a - __half2float(h0));
    __half l1 = __float2half_rn(b - __half2float(h1));
    __half2 H = __halves2half2(h0, h1), L = __halves2half2(l0, l1);
    hi = *reinterpret_cast<uint32_t*>(&H);
    lo = *reinterpret_cast<uint32_t*>(&L);
}

static __device__ __forceinline__ void mma16816(float* d, uint32_t a0, uint32_t a1,
                                                uint32_t a2, uint32_t a3,
                                                uint32_t b0, uint32_t b1)
{
    asm volatile("mma.sync.aligned.m16n8k16.row.col.f32.f16.f16.f32 "
                 "{%0,%1,%2,%3}, {%4,%5,%6,%7}, {%8,%9}, {%0,%1,%2,%3};"
                 : "+f"(d[0]), "+f"(d[1]), "+f"(d[2]), "+f"(d[3])
                 : "r"(a0), "r"(a1), "r"(a2), "r"(a3), "r"(b0), "r"(b1));
}

static __device__ __forceinline__ float wu_elem(const float* __restrict__ W,
                                                const float* __restrict__ U,
                                                int Kin, int k, int gcol)
{
    return (k < Kin) ? W[(size_t)k * 1024 + gcol] : U[(size_t)(k - Kin) * 1024 + gcol];
}

static __device__ __forceinline__ unsigned ld_acq(const unsigned* p)
{
    unsigned v;
    asm volatile("ld.acquire.gpu.global.u32 %0, [%1];" : "=r"(v) : "l"(p) : "memory");
    return v;
}
static __device__ __forceinline__ void st_rel(unsigned* p, unsigned v)
{
    asm volatile("st.release.gpu.global.u32 [%0], %1;" :: "l"(p), "r"(v) : "memory");
}
static __device__ __forceinline__ void st_cg_u16(unsigned short* p, unsigned short v)
{
    asm volatile("st.global.cg.u16 [%0], %1;" :: "l"(p), "h"(v) : "memory");
}
static __device__ __forceinline__ uint32_t ld_cg_u32(const uint32_t* p)
{
    uint32_t v;
    asm volatile("ld.global.cg.u32 %0, [%1];" : "=r"(v) : "l"(p));
    return v;
}

static __device__ __forceinline__ float sigx(float x)
{
    return __fdividef(1.0f, 1.0f + __expf(-x));
}
static __device__ __forceinline__ float tanhx(float x)
{
    return __fdividef(2.0f, 1.0f + __expf(-2.0f * x)) - 1.0f;
}

// ---------------------------------------------------------------------------
// Persistent tensor-core masked-LSTM layer. 128 blocks: bg=blockIdx&3 (16 rows),
// cg=blockIdx>>2 (8 units -> 32 gate cols). 8 warps split K; warp w's h-slice =
// units [32w,32w+32) = outputs of producer blocks (bg, 4w..4w+3) -> per-warp
// flag poll, fragment-direct ld.cg into mma registers. x software-pipelined.
// ---------------------------------------------------------------------------
template <int LAYER>
__global__ void __launch_bounds__(256, 1)
lstm_tc(const float* __restrict__ x0,
        const float* __restrict__ W, const float* __restrict__ U,
        const float* __restrict__ bias)
{
    constexpr int XSTEPS = (LAYER == 0) ? 1 : 2;
    constexpr int KIN    = 128 * XSTEPS;
    constexpr int KSTEPS = XSTEPS + 2;

    __shared__ float    p_sh[8 * 16 * 36];
    __shared__ uint32_t msk_sh[16 * 32];

    const int tid  = threadIdx.x;
    const int w    = tid >> 5;
    const int lane = tid & 31;
    const int bg   = blockIdx.x & 3;
    const int cg   = blockIdx.x >> 2;
    const int row0 = bg * 16;
    const int q    = lane & 3;
    const int nl   = lane >> 2;

    // ---- stage mask bits (2KB, once) ----
    for (int i = tid; i < 512; i += 256)
        msk_sh[i] = g_mbits[(row0 + (i >> 5)) * 32 + (i & 31)];

    // ---- B (weight) fragments in registers, hi/lo split ----
    auto kbase = [&](int s) -> int {
        return (s < XSTEPS) ? (w * (KIN / 8) + 16 * s)
                            : (KIN + w * 32 + 16 * (s - XSTEPS));
    };
    uint32_t Bhi[4][KSTEPS][2], Blo[4][KSTEPS][2];
    #pragma unroll
    for (int i = 0; i < 4; i++) {
        int gcol = i * 256 + cg * 8 + nl;
        #pragma unroll
        for (int s = 0; s < KSTEPS; s++) {
            int kb = kbase(s) + 2 * q;
            split2(wu_elem(W, U, KIN, kb,     gcol),
                   wu_elem(W, U, KIN, kb + 1, gcol), Bhi[i][s][0], Blo[i][s][0]);
            split2(wu_elem(W, U, KIN, kb + 8, gcol),
                   wu_elem(W, U, KIN, kb + 9, gcol), Bhi[i][s][1], Blo[i][s][1]);
        }
    }

    // ---- gate-thread constants/state (tid<128: row gr, unit gu) ----
    const int gr = tid >> 3, gu = tid & 7;
    float bias4[4] = {0, 0, 0, 0};
    if (tid < 128) {
        #pragma unroll
        for (int g = 0; g < 4; g++) bias4[g] = bias[g * 256 + cg * 8 + gu];
    }
    float c_reg = 0.0f, h_reg = 0.0f;

    unsigned* myflag = &g_flag[LAYER * 128 + bg * 32 + cg];
    const unsigned* pollflag = &g_flag[LAYER * 128 + bg * 32 + 4 * w];

    const uint32_t* seq_in_hi = (LAYER == 1) ? g_sA_hi : g_sB_hi;
    const uint32_t* seq_in_lo = (LAYER == 1) ? g_sA_lo : g_sB_lo;
    uint32_t* seq_out_hi = (LAYER == 0) ? g_sA_hi : g_sB_hi;
    uint32_t* seq_out_lo = (LAYER == 0) ? g_sA_lo : g_sB_lo;

    // ---- x raw pipeline registers (loaded one step ahead) ----
    float2   xrf[4];                 // LAYER 0
    uint32_t xrh[2][4], xrl[2][4];   // LAYER 1/2

    auto load_x = [&](int tt) {
        if (LAYER == 0) {
            const float* xp  = x0 + ((size_t)(row0 + nl) * T_SEQ + tt) * 128 + w * 16;
            const float* xp8 = x0 + ((size_t)(row0 + nl + 8) * T_SEQ + tt) * 128 + w * 16;
            xrf[0] = *reinterpret_cast<const float2*>(xp  + 2 * q);
            xrf[1] = *reinterpret_cast<const float2*>(xp8 + 2 * q);
            xrf[2] = *reinterpret_cast<const float2*>(xp  + 8 + 2 * q);
            xrf[3] = *reinterpret_cast<const float2*>(xp8 + 8 + 2 * q);
        } else {
            int base = sidx(tt, bg, w, 0, 0, 0, 0);
            #pragma unroll
            for (int s = 0; s < 2; s++) {
                xrh[s][0] = seq_in_hi[base + s * 128 + q * 16 + nl];
                xrh[s][1] = seq_in_hi[base + s * 128 + q * 16 + nl + 8];
                xrh[s][2] = seq_in_hi[base + s * 128 + 64 + q * 16 + nl];
                xrh[s][3] = seq_in_hi[base + s * 128 + 64 + q * 16 + nl + 8];
                xrl[s][0] = seq_in_lo[base + s * 128 + q * 16 + nl];
                xrl[s][1] = seq_in_lo[base + s * 128 + q * 16 + nl + 8];
                xrl[s][2] = seq_in_lo[base + s * 128 + 64 + q * 16 + nl];
                xrl[s][3] = seq_in_lo[base + s * 128 + 64 + q * 16 + nl + 8];
            }
        }
    };

    load_x(0);

    for (int t = 0; t < T_SEQ; t++) {
        // ---- materialize current x fragments, then prefetch next step's raw x ----
        uint32_t fxh[XSTEPS][4], fxl[XSTEPS][4];
        if (LAYER == 0) {
            #pragma unroll
            for (int j = 0; j < 4; j++) split2(xrf[j].x, xrf[j].y, fxh[0][j], fxl[0][j]);
        } else {
            #pragma unroll
            for (int s = 0; s < 2; s++)
                #pragma unroll
                for (int j = 0; j < 4; j++) { fxh[s][j] = xrh[s][j]; fxl[s][j] = xrl[s][j]; }
        }
        if (t + 1 < T_SEQ) load_x(t + 1);

        // ---- x-part MMAs (off the h critical chain) ----
        float D[4][4];
        #pragma unroll
        for (int i = 0; i < 4; i++)
            #pragma unroll
            for (int j = 0; j < 4; j++) D[i][j] = 0.0f;

        #pragma unroll
        for (int s = 0; s < XSTEPS; s++)
            #pragma unroll
            for (int i = 0; i < 4; i++) {
                mma16816(D[i], fxh[s][0], fxh[s][1], fxh[s][2], fxh[s][3],
                         Bhi[i][s][0], Bhi[i][s][1]);
                mma16816(D[i], fxl[s][0], fxl[s][1], fxl[s][2], fxl[s][3],
                         Bhi[i][s][0], Bhi[i][s][1]);
                mma16816(D[i], fxh[s][0], fxh[s][1], fxh[s][2], fxh[s][3],
                         Blo[i][s][0], Blo[i][s][1]);
            }

        // ---- per-warp: wait for this warp's 4 producers, then h-frag loads + MMAs ----
        if (t > 0) {
            unsigned tgt = (unsigned)t;
            for (;;) {
                unsigned v = (lane < 4) ? ld_acq(pollflag + lane) : tgt;
                if (__all_sync(0xffffffffu, v >= tgt)) break;
            }
            int p = t & 1;
            int hb = hidx(p, bg, w, 0, 0, 0, 0);
            uint32_t ahh[2][4], ahl[2][4];
            #pragma unroll
            for (int s = 0; s < 2; s++) {
                ahh[s][0] = ld_cg_u32(&g_hf_hi[hb + s * 128 + q * 16 + nl]);
                ahh[s][1] = ld_cg_u32(&g_hf_hi[hb + s * 128 + q * 16 + nl + 8]);
                ahh[s][2] = ld_cg_u32(&g_hf_hi[hb + s * 128 + 64 + q * 16 + nl]);
                ahh[s][3] = ld_cg_u32(&g_hf_hi[hb + s * 128 + 64 + q * 16 + nl + 8]);
                ahl[s][0] = ld_cg_u32(&g_hf_lo[hb + s * 128 + q * 16 + nl]);
                ahl[s][1] = ld_cg_u32(&g_hf_lo[hb + s * 128 + q * 16 + nl + 8]);
                ahl[s][2] = ld_cg_u32(&g_hf_lo[hb + s * 128 + 64 + q * 16 + nl]);
                ahl[s][3] = ld_cg_u32(&g_hf_lo[hb + s * 128 + 64 + q * 16 + nl + 8]);
            }
            #pragma unroll
            for (int s = 0; s < 2; s++) {
                int ks = XSTEPS + s;
                #pragma unroll
                for (int i = 0; i < 4; i++) {
                    mma16816(D[i], ahh[s][0], ahh[s][1], ahh[s][2], ahh[s][3],
                             Bhi[i][ks][0], Bhi[i][ks][1]);
                    mma16816(D[i], ahl[s][0], ahl[s][1], ahl[s][2], ahl[s][3],
                             Bhi[i][ks][0], Bhi[i][ks][1]);
                    mma16816(D[i], ahh[s][0], ahh[s][1], ahh[s][2], ahh[s][3],
                             Blo[i][ks][0], Blo[i][ks][1]);
                }
            }
        }

        // ---- split-K partials to smem ----
        #pragma unroll
        for (int i = 0; i < 4; i++) {
            *reinterpret_cast<float2*>(&p_sh[(w * 16 + nl) * 36 + i * 8 + 2 * q]) =
                make_float2(D[i][0], D[i][1]);
            *reinterpret_cast<float2*>(&p_sh[(w * 16 + nl + 8) * 36 + i * 8 + 2 * q]) =
                make_float2(D[i][2], D[i][3]);
        }
        __syncthreads();

        // ---- gates: reduce partials + state update + publish ----
        if (tid < 128) {
            float z[4];
            #pragma unroll
            for (int g = 0; g < 4; g++) {
                float acc = bias4[g];
                #pragma unroll
                for (int w8 = 0; w8 < 8; w8++)
                    acc += p_sh[(w8 * 16 + gr) * 36 + g * 8 + gu];
                z[g] = acc;
            }
            float si = sigx(z[0]), sf = sigx(z[1]), so = sigx(z[3]);
            float cn = sf * c_reg + si * tanhx(z[2]);
            float hn = so * tanhx(cn);
            bool m = (msk_sh[gr * 32 + (t >> 5)] >> (t & 31)) & 1u;
            if (!m) { cn = c_reg; hn = h_reg; }
            c_reg = cn; h_reg = hn;

            int j  = cg * 8 + gu;
            int jw = j >> 5, js = (j >> 4) & 1, jpg = (j >> 3) & 1, jq = (j >> 1) & 3, jh = j & 1;
            __half hh = __float2half_rn(hn);
            __half hl = __float2half_rn(hn - __half2float(hh));
            int hi_i = hidx((t + 1) & 1, bg, jw, js, jpg, jq, gr);
            st_cg_u16(reinterpret_cast<unsigned short*>(g_hf_hi) + hi_i * 2 + jh,
                      __half_as_ushort(hh));
            st_cg_u16(reinterpret_cast<unsigned short*>(g_hf_lo) + hi_i * 2 + jh,
                      __half_as_ushort(hl));
            if (LAYER < 2) {
                int si_i = sidx(t, bg, jw, js, jpg, jq, gr);
                st_cg_u16(reinterpret_cast<unsigned short*>(seq_out_hi) + si_i * 2 + jh,
                          __half_as_ushort(hh));
                st_cg_u16(reinterpret_cast<unsigned short*>(seq_out_lo) + si_i * 2 + jh,
                          __half_as_ushort(hl));
            }
        }
        __syncthreads();
        if (tid == 0) st_rel(myflag, (unsigned)(t + 1));
    }
}

// ---------------------------------------------------------------------------
__global__ void final_kernel(const float* __restrict__ dw,
                             const float* __restrict__ db,
                             float* __restrict__ out)
{
    int p = blockIdx.x, lane = threadIdx.x;
    int rA = 2 * p, rB = 2 * p + 1;
    float s = 0.0f;
    for (int jj = lane; jj < 128; jj += 32) {
        int j = 2 * jj;
        int jw = j >> 5, js = (j >> 4) & 1, jpg = (j >> 3) & 1, jq = (j >> 1) & 3;
        int iA = hidx(0, rA >> 4, jw, js, jpg, jq, rA & 15);
        int iB = hidx(0, rB >> 4, jw, js, jpg, jq, rB & 15);
        __half2 ah = *reinterpret_cast<__half2*>(&g_hf_hi[iA]);
        __half2 al = *reinterpret_cast<__half2*>(&g_hf_lo[iA]);
        __half2 bh = *reinterpret_cast<__half2*>(&g_hf_hi[iB]);
        __half2 bl = *reinterpret_cast<__half2*>(&g_hf_lo[iB]);
        float a0 = __low2float(ah)  + __low2float(al);
        float a1 = __high2float(ah) + __high2float(al);
        float b0 = __low2float(bh)  + __low2float(bl);
        float b1 = __high2float(bh) + __high2float(bl);
        float d0 = a0 - b0, d1 = a1 - b1;
        s += d0 * d0 + d1 * d1;
    }
    #pragma unroll
    for (int off = 16; off; off >>= 1) s += __shfl_xor_sync(0xffffffffu, s, off);
    if (lane == 0) {
        float dist = sqrtf(s);
        dist = fminf(fmaxf(dist, 1e-7f), 1e7f);
        out[p] = 1.0f / (1.0f + expf(-(dist * dw[0] + db[0])));
    }
}

// ---------------------------------------------------------------------------
extern "C" void kernel_launch(void* const* d_in, const int* in_sizes, int n_in,
                              void* d_out, int out_size)
{
    (void)in_sizes; (void)n_in; (void)out_size;
    const float* x  = (const float*)d_in[0];
    const float* W0 = (const float*)d_in[1];
    const float* U0 = (const float*)d_in[2];
    const float* b0 = (const float*)d_in[3];
    const float* W1 = (const float*)d_in[4];
    const float* U1 = (const float*)d_in[5];
    const float* b1 = (const float*)d_in[6];
    const float* W2 = (const float*)d_in[7];
    const float* U2 = (const float*)d_in[8];
    const float* b2 = (const float*)d_in[9];
    const float* dw = (const float*)d_in[10];
    const float* db = (const float*)d_in[11];
    float* out = (float*)d_out;

    init_kernel<<<8192, 256>>>(x);

    lstm_tc<0><<<128, 256>>>(x, W0, U0, b0);
    lstm_tc<1><<<128, 256>>>(x, W1, U1, b1);
    lstm_tc<2><<<128, 256>>>(x, W2, U2, b2);

    final_kernel<<<32, 32>>>(dw, db, out);
}

// round 10
// speedup vs baseline: 2.1197x; 1.9617x over previous
#include <cuda_runtime.h>
#include <cuda_fp16.h>
#include <cstdint>
#include <cstddef>

#define T_SEQ 1024
#define NROWS 64

// ---------------------------------------------------------------------------
// Exchange buffers (sanctioned __device__ globals).
// frag element u32 = (half k_even, half k_odd)
// h:   [layer3][parity2][bg4][w8][s2][pg2][q4][r16]            (12288 u32)
// seq: [t][bg4][w8][s2][pg2][q4][r16] = t * 8192 u32 (32 MB each)
// ---------------------------------------------------------------------------
__device__ uint32_t g_hf_hi[3 * 2 * 4 * 8 * 2 * 2 * 4 * 16];
__device__ uint32_t g_hf_lo[3 * 2 * 4 * 8 * 2 * 2 * 4 * 16];
__device__ uint32_t g_sA_hi[(size_t)T_SEQ * 8192];
__device__ uint32_t g_sA_lo[(size_t)T_SEQ * 8192];
__device__ uint32_t g_sB_hi[(size_t)T_SEQ * 8192];
__device__ uint32_t g_sB_lo[(size_t)T_SEQ * 8192];
__device__ uint32_t g_mbits[NROWS * 32];
__device__ unsigned g_flag[3 * 4 * 32];          // [layer][bg][cg] = steps done

static __device__ __forceinline__ int hidx3(int l, int p, int bg, int w, int s,
                                            int pg, int q, int r)
{
    return ((((((l * 2 + p) * 4 + bg) * 8 + w) * 2 + s) * 2 + pg) * 4 + q) * 16 + r;
}
static __device__ __forceinline__ int sidx(int t, int bg, int w, int s, int pg, int q, int r)
{
    return (((((t * 4 + bg) * 8 + w) * 2 + s) * 2 + pg) * 4 + q) * 16 + r;
}

// ---------------------------------------------------------------------------
__global__ void init_kernel(const float* __restrict__ x)
{
    if (blockIdx.x == 0)
        for (int i = threadIdx.x; i < 3 * 4 * 32; i += blockDim.x) g_flag[i] = 0u;
    int warp = (int)((blockIdx.x * blockDim.x + threadIdx.x) >> 5);
    int lane = threadIdx.x & 31;
    if (warp < NROWS * T_SEQ) {
        const float4* p = reinterpret_cast<const float4*>(x) + (size_t)warp * 32;
        float4 v = p[lane];
        bool nz = (v.x != 0.0f) || (v.y != 0.0f) || (v.z != 0.0f) || (v.w != 0.0f);
        unsigned bl = __ballot_sync(0xffffffffu, nz);
        if (lane == 0 && bl) {
            int row = warp >> 10, t = warp & 1023;
            atomicOr(&g_mbits[row * 32 + (t >> 5)], 1u << (t & 31));
        }
    }
}

// ---------------------------------------------------------------------------
static __device__ __forceinline__ void split2(float a, float b, uint32_t& hi, uint32_t& lo)
{
    __half h0 = __float2half_rn(a), h1 = __float2half_rn(b);
    __half l0 = __float2half_rn(a - __half2float(h0));
    __half l1 = __float2half_rn(b - __half2float(h1));
    __half2 H = __halves2half2(h0, h1), L = __halves2half2(l0, l1);
    hi = *reinterpret_cast<uint32_t*>(&H);
    lo = *reinterpret_cast<uint32_t*>(&L);
}
static __device__ __forceinline__ void mma16816(float* d, uint32_t a0, uint32_t a1,
                                                uint32_t a2, uint32_t a3,
                                                uint32_t b0, uint32_t b1)
{
    asm volatile("mma.sync.aligned.m16n8k16.row.col.f32.f16.f16.f32 "
                 "{%0,%1,%2,%3}, {%4,%5,%6,%7}, {%8,%9}, {%0,%1,%2,%3};"
                 : "+f"(d[0]), "+f"(d[1]), "+f"(d[2]), "+f"(d[3])
                 : "r"(a0), "r"(a1), "r"(a2), "r"(a3), "r"(b0), "r"(b1));
}
static __device__ __forceinline__ unsigned ld_acq(const unsigned* p)
{
    unsigned v;
    asm volatile("ld.acquire.gpu.global.u32 %0, [%1];" : "=r"(v) : "l"(p) : "memory");
    return v;
}
static __device__ __forceinline__ void st_rel(unsigned* p, unsigned v)
{
    asm volatile("st.release.gpu.global.u32 [%0], %1;" :: "l"(p), "r"(v) : "memory");
}
static __device__ __forceinline__ void st_cg_u16(unsigned short* p, unsigned short v)
{
    asm volatile("st.global.cg.u16 [%0], %1;" :: "l"(p), "h"(v) : "memory");
}
static __device__ __forceinline__ uint32_t ld_cg_u32(const uint32_t* p)
{
    uint32_t v;
    asm volatile("ld.global.cg.u32 %0, [%1];" : "=r"(v) : "l"(p));
    return v;
}
static __device__ __forceinline__ float sigx(float x)
{
    return __fdividef(1.0f, 1.0f + __expf(-x));
}
static __device__ __forceinline__ float tanhx(float x)
{
    return __fdividef(2.0f, 1.0f + __expf(-2.0f * x)) - 1.0f;
}

template <int L> struct LC { static constexpr int val = L; };

// ---------------------------------------------------------------------------
// Fused 3-layer wavefront masked-LSTM. 128 blocks (bg4 x cg32), 256 threads.
// Virtual step v: layer0@t=v, layer1@t=v-2, layer2@t=v-4. Weights (hi/lo f16
// fragments) in smem; h/seq exchange via fragment-layout L2 buffers + flags.
// ---------------------------------------------------------------------------
__global__ void __launch_bounds__(256, 1)
lstm_fused(const float* __restrict__ x0,
           const float* __restrict__ W0, const float* __restrict__ U0, const float* __restrict__ b0,
           const float* __restrict__ W1, const float* __restrict__ U1, const float* __restrict__ b1,
           const float* __restrict__ W2, const float* __restrict__ U2, const float* __restrict__ b2)
{
    extern __shared__ unsigned char smraw[];
    uint32_t* w_frag = reinterpret_cast<uint32_t*>(smraw);       // 45056 u32 (176KB)
    float*    p_sh   = reinterpret_cast<float*>(w_frag + 45056); // [8][16][36]
    uint32_t* msk_sh = reinterpret_cast<uint32_t*>(p_sh + 4608); // [16][32]

    const int tid  = threadIdx.x;
    const int w    = tid >> 5;
    const int lane = tid & 31;
    const int bg   = blockIdx.x & 3;
    const int cg   = blockIdx.x >> 2;
    const int row0 = bg * 16;
    const int q    = lane & 3;
    const int nl   = lane >> 2;

    const float* Ws[3] = {W0, W1, W2};
    const float* Us[3] = {U0, U1, U2};
    const float* bs[3] = {b0, b1, b2};
    const int KSTv[3]  = {3, 4, 4};
    const int XSTv[3]  = {1, 2, 2};
    const int KINv[3]  = {128, 256, 256};
    const int SOFFv[3] = {0, 24, 56};

    for (int i = tid; i < 512; i += 256)
        msk_sh[i] = g_mbits[(row0 + (i >> 5)) * 32 + (i & 31)];

    // ---- build weight fragments in smem (once) ----
    for (int l = 0; l < 3; l++) {
        const float* W = Ws[l];
        const float* U = Us[l];
        const int kin = KINv[l];
        for (int s = 0; s < KSTv[l]; s++) {
            int kb0 = (s < XSTv[l]) ? (w * (kin / 8) + 16 * s)
                                    : (kin + w * 32 + 16 * (s - XSTv[l]));
            for (int i = 0; i < 4; i++) {
                int gcol = i * 256 + cg * 8 + nl;
                int kb = kb0 + 2 * q;
                auto wu = [&](int k) -> float {
                    return (k < kin) ? W[(size_t)k * 1024 + gcol]
                                     : U[(size_t)(k - kin) * 1024 + gcol];
                };
                uint32_t b0h, b0l, b1h, b1l;
                split2(wu(kb),     wu(kb + 1), b0h, b0l);
                split2(wu(kb + 8), wu(kb + 9), b1h, b1l);
                int flat = (SOFFv[l] + w * KSTv[l] + s) * 4 + i;
                *reinterpret_cast<uint4*>(&w_frag[flat * 128 + lane * 4]) =
                    make_uint4(b0h, b1h, b0l, b1l);
            }
        }
    }

    const int gr = tid >> 3, gu = tid & 7;       // gate thread coords (tid<128)
    float bias4[3][4];
    if (tid < 128)
        for (int l = 0; l < 3; l++)
            #pragma unroll
            for (int g = 0; g < 4; g++) bias4[l][g] = bs[l][g * 256 + cg * 8 + gu];

    float c_reg[3] = {0, 0, 0}, h_reg[3] = {0, 0, 0};
    float2   xrf[4];                      // layer0 x pipeline
    uint32_t xsh[2][2][4], xsl[2][2][4];  // layer1/2 x-frag pipeline

    __syncthreads();

    auto poll4 = [&](const unsigned* f, unsigned tgt) {
        for (;;) {
            unsigned v = (lane < 4) ? ld_acq(f + lane) : tgt;
            if (__all_sync(0xffffffffu, v >= tgt)) break;
        }
    };
    auto ld8 = [&](const uint32_t* bhi, const uint32_t* blo, int base,
                   uint32_t hh[2][4], uint32_t hl[2][4]) {
        #pragma unroll
        for (int s = 0; s < 2; s++) {
            int o = base + s * 128 + q * 16 + nl;
            hh[s][0] = ld_cg_u32(bhi + o);      hh[s][1] = ld_cg_u32(bhi + o + 8);
            hh[s][2] = ld_cg_u32(bhi + o + 64); hh[s][3] = ld_cg_u32(bhi + o + 72);
            hl[s][0] = ld_cg_u32(blo + o);      hl[s][1] = ld_cg_u32(blo + o + 8);
            hl[s][2] = ld_cg_u32(blo + o + 64); hl[s][3] = ld_cg_u32(blo + o + 72);
        }
    };
    auto load_x0 = [&](int tt) {
        const float* xp  = x0 + ((size_t)(row0 + nl) * T_SEQ + tt) * 128 + w * 16;
        const float* xp8 = x0 + ((size_t)(row0 + nl + 8) * T_SEQ + tt) * 128 + w * 16;
        xrf[0] = *reinterpret_cast<const float2*>(xp  + 2 * q);
        xrf[1] = *reinterpret_cast<const float2*>(xp8 + 2 * q);
        xrf[2] = *reinterpret_cast<const float2*>(xp  + 8 + 2 * q);
        xrf[3] = *reinterpret_cast<const float2*>(xp8 + 8 + 2 * q);
    };

    auto step = [&](auto lc, int t) {
        constexpr int L  = decltype(lc)::val;
        constexpr int XS = (L == 0) ? 1 : 2;
        constexpr int KS = XS + 2;
        constexpr int SOFF = (L == 0) ? 0 : (L == 1 ? 24 : 56);
        if (t < 0 || t >= T_SEQ) return;

        const uint32_t* sin_hi = (L == 1) ? g_sA_hi : g_sB_hi;
        const uint32_t* sin_lo = (L == 1) ? g_sA_lo : g_sB_lo;
        unsigned* myflag = &g_flag[L * 128 + bg * 32 + cg];
        const unsigned* hflags = &g_flag[L * 128 + bg * 32 + 4 * w];

        // ---- x fragments for step t ----
        uint32_t fxh[XS][4], fxl[XS][4];
        if (L == 0) {
            if (t == 0) load_x0(0);
            #pragma unroll
            for (int j = 0; j < 4; j++) split2(xrf[j].x, xrf[j].y, fxh[0][j], fxl[0][j]);
        } else {
            if (t == 0) {
                poll4(&g_flag[(L - 1) * 128 + bg * 32 + 4 * w], 1u);
                ld8(sin_hi, sin_lo, sidx(0, bg, w, 0, 0, 0, 0), xsh[L - 1], xsl[L - 1]);
            }
            #pragma unroll
            for (int s = 0; s < 2; s++)
                #pragma unroll
                for (int j = 0; j < 4; j++) {
                    fxh[s][j] = xsh[L - 1][s][j];
                    fxl[s][j] = xsl[L - 1][s][j];
                }
        }

        // ---- h poll + fragment loads (t>0) ----
        uint32_t ahh[2][4], ahl[2][4];
        if (t > 0) {
            poll4(hflags, (unsigned)t);
            ld8(g_hf_hi, g_hf_lo, hidx3(L, t & 1, bg, w, 0, 0, 0, 0), ahh, ahl);
        }

        // ---- MMAs (B fragments from smem) ----
        float D[4][4];
        #pragma unroll
        for (int i = 0; i < 4; i++)
            #pragma unroll
            for (int j = 0; j < 4; j++) D[i][j] = 0.0f;

        #pragma unroll
        for (int s = 0; s < XS; s++)
            #pragma unroll
            for (int i = 0; i < 4; i++) {
                uint4 B = *reinterpret_cast<const uint4*>(
                    &w_frag[((SOFF + w * KS + s) * 4 + i) * 128 + lane * 4]);
                mma16816(D[i], fxh[s][0], fxh[s][1], fxh[s][2], fxh[s][3], B.x, B.y);
                mma16816(D[i], fxl[s][0], fxl[s][1], fxl[s][2], fxl[s][3], B.x, B.y);
                mma16816(D[i], fxh[s][0], fxh[s][1], fxh[s][2], fxh[s][3], B.z, B.w);
            }
        if (t > 0) {
            #pragma unroll
            for (int s2 = 0; s2 < 2; s2++) {
                int s = XS + s2;
                #pragma unroll
                for (int i = 0; i < 4; i++) {
                    uint4 B = *reinterpret_cast<const uint4*>(
                        &w_frag[((SOFF + w * KS + s) * 4 + i) * 128 + lane * 4]);
                    mma16816(D[i], ahh[s2][0], ahh[s2][1], ahh[s2][2], ahh[s2][3], B.x, B.y);
                    mma16816(D[i], ahl[s2][0], ahl[s2][1], ahl[s2][2], ahl[s2][3], B.x, B.y);
                    mma16816(D[i], ahh[s2][0], ahh[s2][1], ahh[s2][2], ahh[s2][3], B.z, B.w);
                }
            }
        }

        // ---- split-K partials ----
        #pragma unroll
        for (int i = 0; i < 4; i++) {
            *reinterpret_cast<float2*>(&p_sh[(w * 16 + nl) * 36 + i * 8 + 2 * q]) =
                make_float2(D[i][0], D[i][1]);
            *reinterpret_cast<float2*>(&p_sh[(w * 16 + nl + 8) * 36 + i * 8 + 2 * q]) =
                make_float2(D[i][2], D[i][3]);
        }
        __syncthreads();

        // ---- gates + state + publish ----
        if (tid < 128) {
            float z[4];
            #pragma unroll
            for (int g = 0; g < 4; g++) {
                float acc = bias4[L][g];
                #pragma unroll
                for (int w8 = 0; w8 < 8; w8++)
                    acc += p_sh[(w8 * 16 + gr) * 36 + g * 8 + gu];
                z[g] = acc;
            }
            float si = sigx(z[0]), sf = sigx(z[1]), so = sigx(z[3]);
            float cn = sf * c_reg[L] + si * tanhx(z[2]);
            float hn = so * tanhx(cn);
            bool m = (msk_sh[gr * 32 + (t >> 5)] >> (t & 31)) & 1u;
            if (!m) { cn = c_reg[L]; hn = h_reg[L]; }
            c_reg[L] = cn; h_reg[L] = hn;

            int j  = cg * 8 + gu;
            int jw = j >> 5, js = (j >> 4) & 1, jpg = (j >> 3) & 1, jq = (j >> 1) & 3, jh = j & 1;
            __half hh = __float2half_rn(hn);
            __half hl = __float2half_rn(hn - __half2float(hh));
            int hi_i = hidx3(L, (t + 1) & 1, bg, jw, js, jpg, jq, gr);
            st_cg_u16(reinterpret_cast<unsigned short*>(g_hf_hi) + hi_i * 2 + jh,
                      __half_as_ushort(hh));
            st_cg_u16(reinterpret_cast<unsigned short*>(g_hf_lo) + hi_i * 2 + jh,
                      __half_as_ushort(hl));
            if (L < 2) {
                uint32_t* soh = (L == 0) ? g_sA_hi : g_sB_hi;
                uint32_t* sol = (L == 0) ? g_sA_lo : g_sB_lo;
                int si_i = sidx(t, bg, jw, js, jpg, jq, gr);
                st_cg_u16(reinterpret_cast<unsigned short*>(soh) + si_i * 2 + jh,
                          __half_as_ushort(hh));
                st_cg_u16(reinterpret_cast<unsigned short*>(sol) + si_i * 2 + jh,
                          __half_as_ushort(hl));
            }
        }
        __syncthreads();
        if (tid == 0) st_rel(myflag, (unsigned)(t + 1));

        // ---- prefetch x for t+1 (producer is ~2 virtual steps ahead) ----
        if (t + 1 < T_SEQ) {
            if (L == 0) load_x0(t + 1);
            else {
                poll4(&g_flag[(L - 1) * 128 + bg * 32 + 4 * w], (unsigned)(t + 2));
                ld8(sin_hi, sin_lo, sidx(t + 1, bg, w, 0, 0, 0, 0), xsh[L - 1], xsl[L - 1]);
            }
        }
    };

    for (int v = 0; v < T_SEQ + 4; v++) {
        step(LC<0>{}, v);
        step(LC<1>{}, v - 2);
        step(LC<2>{}, v - 4);
    }
}

// ---------------------------------------------------------------------------
__global__ void final_kernel(const float* __restrict__ dw,
                             const float* __restrict__ db,
                             float* __restrict__ out)
{
    int p = blockIdx.x, lane = threadIdx.x;
    int rA = 2 * p, rB = 2 * p + 1;       // layer2, parity (1024&1)=0
    float s = 0.0f;
    for (int jj = lane; jj < 128; jj += 32) {
        int j = 2 * jj;
        int jw = j >> 5, js = (j >> 4) & 1, jpg = (j >> 3) & 1, jq = (j >> 1) & 3;
        int iA = hidx3(2, 0, rA >> 4, jw, js, jpg, jq, rA & 15);
        int iB = hidx3(2, 0, rB >> 4, jw, js, jpg, jq, rB & 15);
        __half2 ah = *reinterpret_cast<__half2*>(&g_hf_hi[iA]);
        __half2 al = *reinterpret_cast<__half2*>(&g_hf_lo[iA]);
        __half2 bh = *reinterpret_cast<__half2*>(&g_hf_hi[iB]);
        __half2 bl = *reinterpret_cast<__half2*>(&g_hf_lo[iB]);
        float a0 = __low2float(ah)  + __low2float(al);
        float a1 = __high2float(ah) + __high2float(al);
        float b0 = __low2float(bh)  + __low2float(bl);
        float b1 = __high2float(bh) + __high2float(bl);
        float d0 = a0 - b0, d1 = a1 - b1;
        s += d0 * d0 + d1 * d1;
    }
    #pragma unroll
    for (int off = 16; off; off >>= 1) s += __shfl_xor_sync(0xffffffffu, s, off);
    if (lane == 0) {
        float dist = sqrtf(s);
        dist = fminf(fmaxf(dist, 1e-7f), 1e7f);
        out[p] = 1.0f / (1.0f + expf(-(dist * dw[0] + db[0])));
    }
}

// ---------------------------------------------------------------------------
extern "C" void kernel_launch(void* const* d_in, const int* in_sizes, int n_in,
                              void* d_out, int out_size)
{
    (void)in_sizes; (void)n_in; (void)out_size;
    const float* x  = (const float*)d_in[0];
    const float* W0 = (const float*)d_in[1];
    const float* U0 = (const float*)d_in[2];
    const float* b0 = (const float*)d_in[3];
    const float* W1 = (const float*)d_in[4];
    const float* U1 = (const float*)d_in[5];
    const float* b1 = (const float*)d_in[6];
    const float* W2 = (const float*)d_in[7];
    const float* U2 = (const float*)d_in[8];
    const float* b2 = (const float*)d_in[9];
    const float* dw = (const float*)d_in[10];
    const float* db = (const float*)d_in[11];
    float* out = (float*)d_out;

    const size_t smem = 45056u * 4 + 4608u * 4 + 512u * 4;   // 200704 B
    cudaFuncSetAttribute(lstm_fused, cudaFuncAttributeMaxDynamicSharedMemorySize,
                         (int)smem);

    init_kernel<<<8192, 256>>>(x);
    lstm_fused<<<128, 256, smem>>>(x, W0, U0, b0, W1, U1, b1, W2, U2, b2);
    final_kernel<<<32, 32>>>(dw, db, out);
}